// round 3
// baseline (speedup 1.0000x reference)
#include <cuda_runtime.h>

// ---------------------------------------------------------------------------
// RNN_70480413327462: 59-step patch-grid RNN + 9-neighbor center attention.
// R3: 2 patches (4 rows) per warp to amortize weight LDS; triple-lane K
// gather for scores; 147 CTAs x 448 threads, 1 grid barrier per step.
// ---------------------------------------------------------------------------

#define NBLK   147
#define NTHR   448
#define NWARPS 14
#define PP     4096
#define NROWS  8192
#define HH     32
#define TSTEPS 59
#define NOBS   10
#define KPAD   36
#define INV_SQRT_E 0.1714985851425088f   // 1/sqrt(34)

__device__ float g_Q[2][NROWS * KPAD];
__device__ float g_K[2][NROWS * KPAD];
__device__ float g_V[2][NROWS * KPAD];
__device__ unsigned g_arrive = 0;
__device__ volatile unsigned g_gen = 0;

struct Smem {
    float4 Wc[32][17];        // c<8: W_x2h chunk c; c>=8: W_h2h chunk c-8
    float4 Wq[32][9];
    float4 Wk[32][9];
    float4 Wv[32][9];
    float4 Mw[32][9];         // (W_fcsa@W_out)^T chunks (9 used, tail zeroed)
    float4 Wf[32][9];         // W_fc2 chunks (8 used)
    float4 We[6][9];          // ext rows (q32,q33,k32,k33,v32,v33)
    float4 RB[NWARPS][4][18]; // per-row stage: [0..7] inp/ht/o, [8]=o8, [9..16]=h
    float  SC[NWARPS][4][12]; // raw scores per combo
    int    NBS[NWARPS][2][12];// neighbor row offsets (elements) per patch
    unsigned sbase;
};

__device__ __forceinline__ float warpAllSum(float v) {
#pragma unroll
    for (int o = 16; o > 0; o >>= 1) v += __shfl_xor_sync(0xffffffffu, v, o);
    return v;
}

__device__ __forceinline__ float ftanh(float x) {
    float e = __expf(2.f * x);
    return 1.f - __fdividef(2.f, e + 1.f);
}

__device__ __forceinline__ float dot4(float4 a, float4 b) {
    return fmaf(a.x, b.x, fmaf(a.y, b.y, fmaf(a.z, b.z, a.w * b.w)));
}

extern __shared__ unsigned char smem_raw[];

__global__ void __launch_bounds__(NTHR, 1) rnn_kernel(
    const float* __restrict__ x,
    const float* __restrict__ W_x2h, const float* __restrict__ b_x2h,
    const float* __restrict__ W_h2h, const float* __restrict__ b_h2h,
    const float* __restrict__ W_fc2, const float* __restrict__ b_fc2,
    const float* __restrict__ ln_g,  const float* __restrict__ ln_b,
    const float* __restrict__ W_fcsa,const float* __restrict__ b_fcsa,
    const float* __restrict__ W_in,  const float* __restrict__ b_in,
    const float* __restrict__ W_out, const float* __restrict__ b_out,
    float* __restrict__ out)
{
    Smem* sm = reinterpret_cast<Smem*>(smem_raw);
    const int tid = threadIdx.x;

    // ---------------- smem weight init ----------------
    for (int idx = tid; idx < 32 * 16; idx += NTHR) {
        int e = idx >> 4, c = idx & 15;
        const float* src = (c < 8) ? (W_x2h + e * 32 + c * 4)
                                   : (W_h2h + e * 32 + (c - 8) * 4);
        sm->Wc[e][c] = make_float4(src[0], src[1], src[2], src[3]);
    }
    for (int idx = tid; idx < 32 * 8; idx += NTHR) {
        int e = idx >> 3, c = idx & 7, i = c * 4;
        const float* q = W_in + e * 34 + i;
        const float* k = W_in + (34 + e) * 34 + i;
        const float* v = W_in + (68 + e) * 34 + i;
        const float* f = W_fc2 + e * 32 + i;
        sm->Wq[e][c] = make_float4(q[0], q[1], q[2], q[3]);
        sm->Wk[e][c] = make_float4(k[0], k[1], k[2], k[3]);
        sm->Wv[e][c] = make_float4(v[0], v[1], v[2], v[3]);
        sm->Wf[e][c] = make_float4(f[0], f[1], f[2], f[3]);
    }
    for (int idx = tid; idx < 32 * 9; idx += NTHR) {
        int e = idx / 9, c = idx % 9;
        float w[4];
#pragma unroll
        for (int d = 0; d < 4; d++) {
            int f = c * 4 + d;
            float acc = 0.f;
            if (f < 34)
                for (int g = 0; g < 34; g++)
                    acc += W_fcsa[e * 34 + g] * W_out[g * 34 + f];
            w[d] = acc;
        }
        sm->Mw[e][c] = make_float4(w[0], w[1], w[2], w[3]);
    }
    for (int idx = tid; idx < 6 * 8; idx += NTHR) {
        int j = idx >> 3, c = idx & 7;
        int row = (j >> 1) * 34 + 32 + (j & 1);
        const float* src = W_in + row * 34 + c * 4;
        sm->We[j][c] = make_float4(src[0], src[1], src[2], src[3]);
    }
    if (tid == 0) sm->sbase = g_gen;

    const int lane = tid & 31;
    const int wid  = tid >> 5;
    const int pa   = (blockIdx.x * NWARPS + wid) * 2;
    const int pb   = pa + 1;
    const bool active = (pa < PP);

    // ---------------- per-lane constants ----------------
    int pqA = 0, pqB = 0;
    float bqA=0.f,bkA=0.f,bvA=0.f, bqB=0.f,bkB=0.f,bvB=0.f;
    float bcombL=0.f, bfL=0.f, lngL=0.f, lnbL=0.f, bbL=0.f;
    float exC = 0.f; int eoff = 0;
    const int exJ   = lane % 6;        // ext output index
    const int exRow = lane / 6;        // RB row 0..3
    const bool exAct = (lane < 24);

    int roff[4];

    if (active) {
#pragma unroll
        for (int ps = 0; ps < 2; ps++) {
            int p = ps ? pb : pa;
            int r = p >> 6, cI = p & 63;
            float c0 = (float)r  * (1.f / 64.f);
            float c1 = (float)cI * (1.f / 64.f);
            int rc  = min(max(r, 1), 62);
            int ccn = min(max(cI, 1), 62);
            int pq = (rc * 64 + ccn) * KPAD;
            if (ps) pqB = pq; else pqA = pq;
            if (lane < 9)
                sm->NBS[wid][ps][lane] =
                    ((rc + lane / 3 - 1) * 64 + (ccn + lane % 3 - 1)) * KPAD;
            float bq = b_in[lane]      + c0 * W_in[lane * 34 + 32]        + c1 * W_in[lane * 34 + 33];
            float bk = b_in[34 + lane] + c0 * W_in[(34 + lane) * 34 + 32] + c1 * W_in[(34 + lane) * 34 + 33];
            float bv = b_in[68 + lane] + c0 * W_in[(68 + lane) * 34 + 32] + c1 * W_in[(68 + lane) * 34 + 33];
            if (ps) { bqB = bq; bkB = bk; bvB = bv; }
            else    { bqA = bq; bkA = bk; bvA = bv; }
        }
        bcombL = b_x2h[lane] + b_h2h[lane];
        bfL  = b_fc2[lane];
        lngL = ln_g[lane];
        lnbL = ln_b[lane];
        {
            float acc = b_fcsa[lane];
            for (int g = 0; g < 34; g++) acc += b_out[g] * W_fcsa[lane * 34 + g];
            bbL = acc;
        }
        roff[0] = pa * KPAD;
        roff[1] = (PP + pa) * KPAD;
        roff[2] = pb * KPAD;
        roff[3] = (PP + pb) * KPAD;
        if (exAct) {
            int p = (exRow >= 2) ? pb : pa;
            int b = exRow & 1;
            int r = p >> 6, cI = p & 63;
            float c0 = (float)r  * (1.f / 64.f);
            float c1 = (float)cI * (1.f / 64.f);
            int row = (exJ >> 1) * 34 + 32 + (exJ & 1);
            exC = b_in[row] + c0 * W_in[row * 34 + 32] + c1 * W_in[row * 34 + 33];
            eoff = (b * PP + p) * KPAD + 32 + (exJ & 1);
        }
        // zero h staging + QKV row pads (elements 34,35)
#pragma unroll
        for (int i = 0; i < 4; i++)
            ((float*)sm->RB[wid][i])[36 + lane] = 0.f;
        if (lane < 2) {
#pragma unroll
            for (int par = 0; par < 2; par++)
#pragma unroll
                for (int i = 0; i < 4; i++) {
                    size_t o = (size_t)roff[i] + 34 + lane;
                    g_Q[par][o] = 0.f; g_K[par][o] = 0.f; g_V[par][o] = 0.f;
                }
        }
    }
    __syncthreads();

    const unsigned sbase = sm->sbase;
    float4* RB[4];
    float*  RBf[4];
#pragma unroll
    for (int i = 0; i < 4; i++) {
        RB[i]  = sm->RB[wid][i];
        RBf[i] = (float*)RB[i];
    }

    // score-pass lane mapping
    const int mI = lane / 3;
    const int jI = lane - mI * 3;
    const bool pAct = (lane < 27);
    // vmix lane mapping
    const int half = lane >> 4;
    const int cc   = lane & 15;
    const bool vAct = (cc < 9);
    const int bAddH = half * (PP * KPAD);

    float h[4]  = {0.f, 0.f, 0.f, 0.f};
    float ht[4] = {0.f, 0.f, 0.f, 0.f};

    for (int t = 0; t < TSTEPS; t++) {
        const int buf = t & 1;
        float* Qb = g_Q[buf];
        float* Kb = g_K[buf];
        float* Vb = g_V[buf];

        // =============== PHASE 1: RNN cell + QKV produce ===============
        if (active) {
            if (t < NOBS) {
                const float* xb = x + (size_t)t * NROWS * HH;
                RBf[0][lane] = xb[pa * HH + lane];
                RBf[1][lane] = xb[(PP + pa) * HH + lane];
                RBf[2][lane] = xb[pb * HH + lane];
                RBf[3][lane] = xb[(PP + pb) * HH + lane];
            }
            __syncwarp();

            float a0 = bcombL, a1 = bcombL, a2 = bcombL, a3 = bcombL;
#pragma unroll
            for (int c = 0; c < 16; c++) {
                float4 w  = sm->Wc[lane][c];
                int dc = (c < 8) ? c : c + 1;
                a0 += dot4(RB[0][dc], w);
                a1 += dot4(RB[1][dc], w);
                a2 += dot4(RB[2][dc], w);
                a3 += dot4(RB[3][dc], w);
            }
            ht[0] = ftanh(a0); ht[1] = ftanh(a1);
            ht[2] = ftanh(a2); ht[3] = ftanh(a3);

            __syncwarp();
#pragma unroll
            for (int i = 0; i < 4; i++) RBf[i][lane] = ht[i];
            __syncwarp();

            float q0=bqA,k0=bkA,v0=bvA, q1=bqA,k1=bkA,v1=bvA;
            float q2=bqB,k2=bkB,v2=bvB, q3=bqB,k3=bkB,v3=bvB;
#pragma unroll
            for (int c = 0; c < 8; c++) {
                float4 wq = sm->Wq[lane][c];
                float4 wk = sm->Wk[lane][c];
                float4 wv = sm->Wv[lane][c];
                float4 t0 = RB[0][c], t1 = RB[1][c], t2 = RB[2][c], t3 = RB[3][c];
                q0 += dot4(t0, wq); k0 += dot4(t0, wk); v0 += dot4(t0, wv);
                q1 += dot4(t1, wq); k1 += dot4(t1, wk); v1 += dot4(t1, wv);
                q2 += dot4(t2, wq); k2 += dot4(t2, wk); v2 += dot4(t2, wv);
                q3 += dot4(t3, wq); k3 += dot4(t3, wk); v3 += dot4(t3, wv);
            }
            Qb[roff[0]+lane]=q0; Kb[roff[0]+lane]=k0; Vb[roff[0]+lane]=v0;
            Qb[roff[1]+lane]=q1; Kb[roff[1]+lane]=k1; Vb[roff[1]+lane]=v1;
            Qb[roff[2]+lane]=q2; Kb[roff[2]+lane]=k2; Vb[roff[2]+lane]=v2;
            Qb[roff[3]+lane]=q3; Kb[roff[3]+lane]=k3; Vb[roff[3]+lane]=v3;

            if (exAct) {
                float ex = exC;
                const float4* hp = RB[exRow];
#pragma unroll
                for (int c = 0; c < 8; c++)
                    ex += dot4(hp[c], sm->We[exJ][c]);
                float* eb = (exJ < 2) ? Qb : ((exJ < 4) ? Kb : Vb);
                eb[eoff] = ex;
            }
        }

        // =============== GRID BARRIER ===============
        {
            __threadfence();
            __syncthreads();
            if (tid == 0) {
                unsigned want = sbase + (unsigned)t + 1u;
                unsigned tk = atomicAdd(&g_arrive, 1u);
                if ((tk % (unsigned)NBLK) == (unsigned)(NBLK - 1)) {
                    g_gen = want;
                } else {
                    while ((int)(g_gen - want) < 0) __nanosleep(32);
                }
            }
            __syncthreads();
            __threadfence();
        }

        // =============== PHASE 2: attention + update + pred ===============
        if (active) {
            // --- 4 score passes: lane 3m+j handles 12 elems of q.k_nb[m] ---
#pragma unroll
            for (int cb = 0; cb < 4; cb++) {
                const int patchSel = cb >> 1;
                const int bAdd = (cb & 1) * (PP * KPAD);
                const int qoff = (patchSel ? pqB : pqA) + bAdd;
                float d = 0.f;
                if (pAct) {
                    const int koff = sm->NBS[wid][patchSel][mI] + bAdd;
                    const float4* qp = (const float4*)(Qb + qoff);
                    const float4* kp = (const float4*)(Kb + koff);
#pragma unroll
                    for (int i = 0; i < 3; i++) {
                        int ch = 3 * i + jI;
                        float4 qc = __ldcg(qp + ch);
                        float4 kc = __ldcg(kp + ch);
                        d += dot4(qc, kc);
                    }
                }
                float d1 = __shfl_sync(0xffffffffu, d, (lane + 1) & 31);
                float d2 = __shfl_sync(0xffffffffu, d, (lane + 2) & 31);
                if (pAct && jI == 0) sm->SC[wid][cb][mI] = d + d1 + d2;
            }
            __syncwarp();

            // --- vmix: halves = batch, lane&15 = o chunk; 2 patch passes ---
#pragma unroll
            for (int ps = 0; ps < 2; ps++) {
                const int cbIdx = ps * 2 + half;
                float sv[9];
#pragma unroll
                for (int m = 0; m < 9; m++) sv[m] = sm->SC[wid][cbIdx][m];
                float mx = sv[0];
#pragma unroll
                for (int m = 1; m < 9; m++) mx = fmaxf(mx, sv[m]);
                float ssum = 0.f;
#pragma unroll
                for (int m = 0; m < 9; m++) {
                    sv[m] = __expf((sv[m] - mx) * INV_SQRT_E);
                    ssum += sv[m];
                }
                float inv = __fdividef(1.f, ssum);
                float4 o4 = make_float4(0.f, 0.f, 0.f, 0.f);
#pragma unroll
                for (int m = 0; m < 9; m++) {
                    int nm = sm->NBS[wid][ps][m];
                    if (vAct) {
                        float4 vv = __ldcg((const float4*)(Vb + nm + bAddH) + cc);
                        float w = sv[m] * inv;
                        o4.x = fmaf(w, vv.x, o4.x);
                        o4.y = fmaf(w, vv.y, o4.y);
                        o4.z = fmaf(w, vv.z, o4.z);
                        o4.w = fmaf(w, vv.w, o4.w);
                    }
                }
                if (vAct) RB[ps * 2 + half][cc] = o4;
            }
            __syncwarp();

            // --- fused out-proj + fcsa ---
            float d0 = bbL, d1 = bbL, d2 = bbL, d3 = bbL;
#pragma unroll
            for (int c = 0; c < 9; c++) {
                float4 wt = sm->Mw[lane][c];
                d0 += dot4(RB[0][c], wt);
                d1 += dot4(RB[1][c], wt);
                d2 += dot4(RB[2][c], wt);
                d3 += dot4(RB[3][c], wt);
            }
            h[0] = ht[0] + d0; h[1] = ht[1] + d1;
            h[2] = ht[2] + d2; h[3] = ht[3] + d3;
#pragma unroll
            for (int i = 0; i < 4; i++) RBf[i][36 + lane] = h[i];
            __syncwarp();

            // --- fc2 + layernorm -> pred ---
            float y0 = bfL, y1 = bfL, y2 = bfL, y3 = bfL;
#pragma unroll
            for (int c = 0; c < 8; c++) {
                float4 wt = sm->Wf[lane][c];
                y0 += dot4(RB[0][9 + c], wt);
                y1 += dot4(RB[1][9 + c], wt);
                y2 += dot4(RB[2][9 + c], wt);
                y3 += dot4(RB[3][9 + c], wt);
            }
            float yv[4] = {y0, y1, y2, y3};
            float pred[4];
#pragma unroll
            for (int i = 0; i < 4; i++) {
                float m = warpAllSum(yv[i]) * (1.f / 32.f);
                float dd = yv[i] - m;
                float var = warpAllSum(dd * dd) * (1.f / 32.f);
                pred[i] = dd * rsqrtf(var + 1e-5f) * lngL + lnbL;
            }
#pragma unroll
            for (int i = 0; i < 4; i++) RBf[i][lane] = pred[i];

            float* ob = out + (size_t)t * NROWS * HH;
            ob[pa * HH + lane]        = pred[0];
            ob[(PP + pa) * HH + lane] = pred[1];
            ob[pb * HH + lane]        = pred[2];
            ob[(PP + pb) * HH + lane] = pred[3];
        }
    }
}

extern "C" void kernel_launch(void* const* d_in, const int* in_sizes, int n_in,
                              void* d_out, int out_size) {
    (void)in_sizes; (void)n_in; (void)out_size;
    cudaFuncSetAttribute(rnn_kernel, cudaFuncAttributeMaxDynamicSharedMemorySize,
                         (int)sizeof(Smem));
    rnn_kernel<<<NBLK, NTHR, sizeof(Smem)>>>(
        (const float*)d_in[0],
        (const float*)d_in[1],  (const float*)d_in[2],
        (const float*)d_in[3],  (const float*)d_in[4],
        (const float*)d_in[5],  (const float*)d_in[6],
        (const float*)d_in[7],  (const float*)d_in[8],
        (const float*)d_in[9],  (const float*)d_in[10],
        (const float*)d_in[11], (const float*)d_in[12],
        (const float*)d_in[13], (const float*)d_in[14],
        (float*)d_out);
}

// round 4
// speedup vs baseline: 1.0484x; 1.0484x over previous
#include <cuda_runtime.h>

// ---------------------------------------------------------------------------
// RNN_70480413327462: 59-step patch-grid RNN + 9-neighbor center attention.
// R4: 2-warp teams, output-split GEMVs over 4 rows -> 4-row weight
// amortization at 28 warps/SM. Named team barriers. 1 grid barrier/step.
// ---------------------------------------------------------------------------

#define NBLK   148
#define NTHR   896
#define NTEAMS 14
#define PP     4096
#define NROWS  8192
#define HH     32
#define TSTEPS 59
#define NOBS   10
#define KPAD   36
#define PPK    (PP * KPAD)
#define INV_SQRT_E 0.1714985851425088f   // 1/sqrt(34)

__device__ float g_Q[2][NROWS * KPAD];
__device__ float g_K[2][NROWS * KPAD];
__device__ float g_V[2][NROWS * KPAD];
__device__ unsigned g_arrive = 0;
__device__ volatile unsigned g_gen = 0;

struct Smem {
    float4 Wc[32][17];        // RNN: c<8 W_x2h chunk c, c>=8 W_h2h chunk c-8 (stride 17)
    float4 Wq[32][9];         // stride 9 => 2-phase conflict-free pair-broadcast
    float4 Wk[32][9];
    float4 Wv[32][9];
    float4 Mw[32][9];         // (W_fcsa@W_out)^T chunks over f (9 used)
    float4 Wf[32][9];         // W_fc2 chunks (8 used)
    float4 We[6][9];          // ext rows (q32,q33,k32,k33,v32,v33)
    float4 RB[NTEAMS][4][18]; // [0..8] inp/ht/o chunks, [9..16] h chunks
    int    NBS[NTEAMS][2][12];// [whalf(=patch)] 9 neighbor row offsets
    unsigned sbase;
};

__device__ __forceinline__ float warpAllSum(float v) {
#pragma unroll
    for (int o = 16; o > 0; o >>= 1) v += __shfl_xor_sync(0xffffffffu, v, o);
    return v;
}

__device__ __forceinline__ float ftanh(float x) {
    float e = __expf(2.f * x);
    return 1.f - __fdividef(2.f, e + 1.f);
}

__device__ __forceinline__ float dot4(float4 a, float4 b) {
    return fmaf(a.x, b.x, fmaf(a.y, b.y, fmaf(a.z, b.z, a.w * b.w)));
}

extern __shared__ unsigned char smem_raw[];

__global__ void __launch_bounds__(NTHR, 1) rnn_kernel(
    const float* __restrict__ x,
    const float* __restrict__ W_x2h, const float* __restrict__ b_x2h,
    const float* __restrict__ W_h2h, const float* __restrict__ b_h2h,
    const float* __restrict__ W_fc2, const float* __restrict__ b_fc2,
    const float* __restrict__ ln_g,  const float* __restrict__ ln_b,
    const float* __restrict__ W_fcsa,const float* __restrict__ b_fcsa,
    const float* __restrict__ W_in,  const float* __restrict__ b_in,
    const float* __restrict__ W_out, const float* __restrict__ b_out,
    float* __restrict__ out)
{
    Smem* sm = reinterpret_cast<Smem*>(smem_raw);
    const int tid = threadIdx.x;

    // ---------------- smem weight init ----------------
    for (int idx = tid; idx < 32 * 16; idx += NTHR) {
        int e = idx >> 4, c = idx & 15;
        const float* src = (c < 8) ? (W_x2h + e * 32 + c * 4)
                                   : (W_h2h + e * 32 + (c - 8) * 4);
        sm->Wc[e][c] = make_float4(src[0], src[1], src[2], src[3]);
    }
    for (int idx = tid; idx < 32 * 8; idx += NTHR) {
        int e = idx >> 3, c = idx & 7, i = c * 4;
        const float* q = W_in + e * 34 + i;
        const float* k = W_in + (34 + e) * 34 + i;
        const float* v = W_in + (68 + e) * 34 + i;
        const float* f = W_fc2 + e * 32 + i;
        sm->Wq[e][c] = make_float4(q[0], q[1], q[2], q[3]);
        sm->Wk[e][c] = make_float4(k[0], k[1], k[2], k[3]);
        sm->Wv[e][c] = make_float4(v[0], v[1], v[2], v[3]);
        sm->Wf[e][c] = make_float4(f[0], f[1], f[2], f[3]);
    }
    for (int idx = tid; idx < 32 * 9; idx += NTHR) {
        int e = idx / 9, c = idx % 9;
        float w[4];
#pragma unroll
        for (int d = 0; d < 4; d++) {
            int f = c * 4 + d;
            float acc = 0.f;
            if (f < 34)
                for (int g = 0; g < 34; g++)
                    acc += W_fcsa[e * 34 + g] * W_out[g * 34 + f];
            w[d] = acc;
        }
        sm->Mw[e][c] = make_float4(w[0], w[1], w[2], w[3]);
    }
    for (int idx = tid; idx < 6 * 8; idx += NTHR) {
        int j = idx >> 3, c = idx & 7;
        int row = (j >> 1) * 34 + 32 + (j & 1);
        const float* src = W_in + row * 34 + c * 4;
        sm->We[j][c] = make_float4(src[0], src[1], src[2], src[3]);
    }
    if (tid == 0) sm->sbase = g_gen;

    const int lane  = tid & 31;
    const int wid   = tid >> 5;
    const int team  = wid >> 1;
    const int whalf = wid & 1;
    const int barId = team + 1;           // named barriers 1..14
    const int tg    = blockIdx.x * NTEAMS + team;
    const int pa    = tg * 2;
    const int pb    = pa + 1;
    const bool active = (pa < PP);

    const int rloc = lane >> 4;           // batch within item
    const int eloc = lane & 15;
    const int eMy  = whalf * 16 + eloc;   // output element this lane owns

    // row index r = 2*patchSel + batch; global row:
    //   grow(r) = (r&1)*PP + pa + (r>>1)
    const int it0Row = rloc;              // patch A, batch rloc
    const int it1Row = 2 + rloc;          // patch B, batch rloc
    const int fr0    = 2 * whalf;         // fc2/ext/x rows owned by this warp
    const int fr1    = fr0 + 1;

    // ---------------- per-lane constants ----------------
    float bcomb=0.f, bb=0.f, bf=0.f, lng=0.f, lnb=0.f;
    float bqA=0.f,bkA=0.f,bvA=0.f, bqB=0.f,bkB=0.f,bvB=0.f;
    float exC = 0.f;
    int   eoffG = 0;
    int   pqMine = 0, nbS = 0;
    int   qkOff0 = 0, qkOff1 = 0;
    int   growF0 = 0, growF1 = 0;

    const int mI = lane / 3;
    const int jI = lane - mI * 3;
    const bool pAct = (lane < 27);
    const bool vAct = (lane < 9);
    const int  exJ  = lane % 6;
    const bool exAct = (lane < 12);

    if (active) {
        float c0A, c1A, c0B, c1B;
        {
            int r = pa >> 6, cI = pa & 63;
            c0A = (float)r * (1.f / 64.f);
            c1A = (float)cI * (1.f / 64.f);
        }
        {
            int r = pb >> 6, cI = pb & 63;
            c0B = (float)r * (1.f / 64.f);
            c1B = (float)cI * (1.f / 64.f);
        }
        {   // own patch (whalf==0 -> A, whalf==1 -> B): shifted center + neighbors
            int p = whalf ? pb : pa;
            int r = p >> 6, cI = p & 63;
            int rc  = min(max(r, 1), 62);
            int ccn = min(max(cI, 1), 62);
            pqMine = (rc * 64 + ccn) * KPAD;
            if (lane < 9)
                sm->NBS[team][whalf][lane] =
                    ((rc + lane / 3 - 1) * 64 + (ccn + lane % 3 - 1)) * KPAD;
        }
        bcomb = b_x2h[eMy] + b_h2h[eMy];
        bqA = b_in[eMy]      + c0A * W_in[eMy * 34 + 32]        + c1A * W_in[eMy * 34 + 33];
        bkA = b_in[34 + eMy] + c0A * W_in[(34 + eMy) * 34 + 32] + c1A * W_in[(34 + eMy) * 34 + 33];
        bvA = b_in[68 + eMy] + c0A * W_in[(68 + eMy) * 34 + 32] + c1A * W_in[(68 + eMy) * 34 + 33];
        bqB = b_in[eMy]      + c0B * W_in[eMy * 34 + 32]        + c1B * W_in[eMy * 34 + 33];
        bkB = b_in[34 + eMy] + c0B * W_in[(34 + eMy) * 34 + 32] + c1B * W_in[(34 + eMy) * 34 + 33];
        bvB = b_in[68 + eMy] + c0B * W_in[(68 + eMy) * 34 + 32] + c1B * W_in[(68 + eMy) * 34 + 33];
        {
            float acc = b_fcsa[eMy];
            for (int g = 0; g < 34; g++) acc += b_out[g] * W_fcsa[eMy * 34 + g];
            bb = acc;
        }
        bf  = b_fc2[lane];
        lng = ln_g[lane];
        lnb = ln_b[lane];

        if (exAct) {   // ext outputs for this warp's own patch rows
            int rExt = fr0 + (lane / 6);            // row r index
            int extrow = (exJ >> 1) * 34 + 32 + (exJ & 1);
            float c0 = whalf ? c0B : c0A;
            float c1 = whalf ? c1B : c1A;
            exC = b_in[extrow] + c0 * W_in[extrow * 34 + 32] + c1 * W_in[extrow * 34 + 33];
            int growE = (rExt & 1) * PP + pa + (rExt >> 1);
            eoffG = growE * KPAD + 32 + (exJ & 1);
        }
        qkOff0 = ((it0Row & 1) * PP + pa + (it0Row >> 1)) * KPAD;
        qkOff1 = ((it1Row & 1) * PP + pa + (it1Row >> 1)) * KPAD;
        growF0 = (fr0 & 1) * PP + pa + (fr0 >> 1);
        growF1 = (fr1 & 1) * PP + pa + (fr1 >> 1);

        // zero h staging region + global q/k/v row pads (elems 34,35), once
        if (whalf == 0) {
#pragma unroll
            for (int r = 0; r < 4; r++)
                ((float*)sm->RB[team][r])[36 + lane] = 0.f;
        }
        if (lane < 2) {
#pragma unroll
            for (int par = 0; par < 2; par++) {
                int offs[2] = {whalf ? qkOff0 : qkOff0, whalf ? qkOff1 : qkOff1};
                // each warp zeros its item rows (covers all 4 rows across team)
#pragma unroll
                for (int i = 0; i < 2; i++) {
                    size_t o = (size_t)(i ? qkOff1 : qkOff0) + 34 + lane;
                    // rloc = 0 for lanes 0-1, so rows 0 and 2; other rows by... 
                    g_Q[par][o] = 0.f; g_K[par][o] = 0.f; g_V[par][o] = 0.f;
                    size_t o2 = o + (size_t)PP * KPAD;   // the batch-1 sibling rows
                    g_Q[par][o2] = 0.f; g_K[par][o2] = 0.f; g_V[par][o2] = 0.f;
                }
            }
        }
    }
    __syncthreads();
    const unsigned sbase = sm->sbase;
    if (active && pAct) nbS = sm->NBS[team][whalf][mI];

    const float4* rb0 = sm->RB[team][it0Row];
    const float4* rb1 = sm->RB[team][it1Row];
    float* rb0f = (float*)rb0;
    float* rb1f = (float*)rb1;
    const float4* rbf0 = sm->RB[team][fr0];
    const float4* rbf1 = sm->RB[team][fr1];
    float* rbf0f = (float*)rbf0;
    float* rbf1f = (float*)rbf1;

    float ht0 = 0.f, ht1 = 0.f;

#define TBAR() asm volatile("bar.sync %0, 64;" :: "r"(barId) : "memory")

    for (int t = 0; t < TSTEPS; t++) {
        const int buf = t & 1;
        float* Qb = g_Q[buf];
        float* Kb = g_K[buf];
        float* Vb = g_V[buf];

        // =============== PHASE 1 ===============
        if (active) {
            if (t < NOBS) {   // stage x for this warp's owned rows
                const float* xb = x + (size_t)t * NROWS * HH;
                rbf0f[lane] = xb[(size_t)growF0 * HH + lane];
                rbf1f[lane] = xb[(size_t)growF1 * HH + lane];
            }
            TBAR();   // A: pred/x staged visible team-wide

            // --- RNN GEMV (output-split, 2 items) ---
            float a0 = bcomb, a1 = bcomb;
#pragma unroll
            for (int c = 0; c < 16; c++) {
                float4 w = sm->Wc[eMy][c];
                int dc = (c < 8) ? c : c + 1;   // h lives at chunks 9..16
                a0 += dot4(rb0[dc], w);
                a1 += dot4(rb1[dc], w);
            }
            ht0 = ftanh(a0);
            ht1 = ftanh(a1);
            rb0f[eMy] = ht0;
            rb1f[eMy] = ht1;
            TBAR();   // B: ht staged

            // --- QKV GEMV (output-split, 2 items) ---
            float q0=bqA,k0=bkA,v0=bvA, q1=bqB,k1=bkB,v1=bvB;
#pragma unroll
            for (int c = 0; c < 8; c++) {
                float4 wq = sm->Wq[eMy][c];
                float4 wk = sm->Wk[eMy][c];
                float4 wv = sm->Wv[eMy][c];
                float4 t0 = rb0[c];
                float4 t1 = rb1[c];
                q0 += dot4(t0, wq); k0 += dot4(t0, wk); v0 += dot4(t0, wv);
                q1 += dot4(t1, wq); k1 += dot4(t1, wk); v1 += dot4(t1, wv);
            }
            Qb[qkOff0 + eMy] = q0; Kb[qkOff0 + eMy] = k0; Vb[qkOff0 + eMy] = v0;
            Qb[qkOff1 + eMy] = q1; Kb[qkOff1 + eMy] = k1; Vb[qkOff1 + eMy] = v1;

            // --- ext elements e=32,33 for this warp's own 2 rows ---
            if (exAct) {
                const float4* hp = sm->RB[team][fr0 + (lane / 6)];
                float ex = exC;
#pragma unroll
                for (int c = 0; c < 8; c++)
                    ex += dot4(hp[c], sm->We[exJ][c]);
                float* eb = (exJ < 2) ? Qb : ((exJ < 4) ? Kb : Vb);
                eb[eoffG] = ex;
            }
        }

        // =============== GRID BARRIER ===============
        {
            __threadfence();
            __syncthreads();
            if (tid == 0) {
                unsigned want = sbase + (unsigned)t + 1u;
                unsigned tk = atomicAdd(&g_arrive, 1u);
                if ((tk % (unsigned)NBLK) == (unsigned)(NBLK - 1)) {
                    g_gen = want;
                } else {
                    while ((int)(g_gen - want) < 0) __nanosleep(32);
                }
            }
            __syncthreads();
            __threadfence();
        }

        // =============== PHASE 2 ===============
        if (active) {
            // --- per-combo (batch b) scores + softmax + vmix, own patch ---
#pragma unroll
            for (int b = 0; b < 2; b++) {
                const int bAdd = b * PPK;
                float d = 0.f;
                if (pAct) {
                    const float4* qp = (const float4*)(Qb + pqMine + bAdd);
                    const float4* kp = (const float4*)(Kb + nbS + bAdd);
#pragma unroll
                    for (int i = 0; i < 3; i++) {
                        int ch = 3 * i + jI;
                        float4 qc = __ldcg(qp + ch);
                        float4 kc = __ldcg(kp + ch);
                        d += dot4(qc, kc);
                    }
                }
                d += __shfl_sync(0xffffffffu, d, (lane + 1) & 31)
                   + __shfl_sync(0xffffffffu, d, (lane + 2) & 31);
                // gather 9 raw scores to all lanes
                float sv[9];
#pragma unroll
                for (int m = 0; m < 9; m++)
                    sv[m] = __shfl_sync(0xffffffffu, d, 3 * m);
                float mx = sv[0];
#pragma unroll
                for (int m = 1; m < 9; m++) mx = fmaxf(mx, sv[m]);
                float ssum = 0.f;
#pragma unroll
                for (int m = 0; m < 9; m++) {
                    sv[m] = __expf((sv[m] - mx) * INV_SQRT_E);
                    ssum += sv[m];
                }
                float inv = __fdividef(1.f, ssum);
                float4 o4 = make_float4(0.f, 0.f, 0.f, 0.f);
#pragma unroll
                for (int m = 0; m < 9; m++) {
                    int nm = __shfl_sync(0xffffffffu, nbS, 3 * m);
                    if (vAct) {
                        float4 vv = __ldcg((const float4*)(Vb + nm + bAdd) + lane);
                        float w = sv[m] * inv;
                        o4.x = fmaf(w, vv.x, o4.x);
                        o4.y = fmaf(w, vv.y, o4.y);
                        o4.z = fmaf(w, vv.z, o4.z);
                        o4.w = fmaf(w, vv.w, o4.w);
                    }
                }
                if (vAct)
                    sm->RB[team][fr0 + b][lane] = o4;   // o chunks for row (ownPatch,b)
            }
            TBAR();   // C: o staged

            // --- fused out-proj + fcsa (output-split, item map) ---
            float d0 = bb, d1 = bb;
#pragma unroll
            for (int c = 0; c < 9; c++) {
                float4 wm = sm->Mw[eMy][c];
                d0 += dot4(rb0[c], wm);
                d1 += dot4(rb1[c], wm);
            }
            float h0 = ht0 + d0;
            float h1 = ht1 + d1;
            rb0f[36 + eMy] = h0;
            rb1f[36 + eMy] = h1;
            TBAR();   // D: h staged

            // --- fc2 + LN for owned rows (lane = e, full row) ---
            float y0 = bf, y1 = bf;
#pragma unroll
            for (int c = 0; c < 8; c++) {
                float4 wf = sm->Wf[lane][c];
                y0 += dot4(rbf0[9 + c], wf);
                y1 += dot4(rbf1[9 + c], wf);
            }
            float m0 = warpAllSum(y0) * (1.f / 32.f);
            float dd0 = y0 - m0;
            float var0 = warpAllSum(dd0 * dd0) * (1.f / 32.f);
            float pred0 = dd0 * rsqrtf(var0 + 1e-5f) * lng + lnb;
            float m1 = warpAllSum(y1) * (1.f / 32.f);
            float dd1 = y1 - m1;
            float var1 = warpAllSum(dd1 * dd1) * (1.f / 32.f);
            float pred1 = dd1 * rsqrtf(var1 + 1e-5f) * lng + lnb;

            rbf0f[lane] = pred0;    // stage as next-step input
            rbf1f[lane] = pred1;

            float* ob = out + (size_t)t * NROWS * HH;
            ob[(size_t)growF0 * HH + lane] = pred0;
            ob[(size_t)growF1 * HH + lane] = pred1;
        }
    }
#undef TBAR
}

extern "C" void kernel_launch(void* const* d_in, const int* in_sizes, int n_in,
                              void* d_out, int out_size) {
    (void)in_sizes; (void)n_in; (void)out_size;
    cudaFuncSetAttribute(rnn_kernel, cudaFuncAttributeMaxDynamicSharedMemorySize,
                         (int)sizeof(Smem));
    rnn_kernel<<<NBLK, NTHR, sizeof(Smem)>>>(
        (const float*)d_in[0],
        (const float*)d_in[1],  (const float*)d_in[2],
        (const float*)d_in[3],  (const float*)d_in[4],
        (const float*)d_in[5],  (const float*)d_in[6],
        (const float*)d_in[7],  (const float*)d_in[8],
        (const float*)d_in[9],  (const float*)d_in[10],
        (const float*)d_in[11], (const float*)d_in[12],
        (const float*)d_in[13], (const float*)d_in[14],
        (float*)d_out);
}